// round 13
// baseline (speedup 1.0000x reference)
#include <cuda_runtime.h>
#include <cuda_fp16.h>

#define RES    512
#define NCOMP  64
#define NPTS_MAX 1048576
#define NBIN   32768          // 1024 (x,y)-Morton2D bins * 32 z-bins

// Channel-last fp16 scratch: [plane][y][x][c]  = 100.5 MB
__device__ __half g_planeT[3ull * RES * RES * NCOMP];
// Sort scratch
__device__ unsigned g_binCnt[NBIN];
__device__ unsigned g_binCursor[NBIN];
__device__ float4   g_sorted[NPTS_MAX];   // (x, y, z, orig_idx bits)

// ---------------- 256-bit accessors (sm_103a evict hints need v8.b32) ------
__device__ __forceinline__ void ldg_256_el(const void* p, unsigned* v) {
    asm("ld.global.nc.L2::evict_last.v8.b32 {%0,%1,%2,%3,%4,%5,%6,%7}, [%8];"
        : "=r"(v[0]), "=r"(v[1]), "=r"(v[2]), "=r"(v[3]),
          "=r"(v[4]), "=r"(v[5]), "=r"(v[6]), "=r"(v[7])
        : "l"(p));
}
__device__ __forceinline__ void stg_256_el(void* p, const unsigned* v) {
    asm volatile("st.global.L2::evict_last.v8.b32 [%0], {%1,%2,%3,%4,%5,%6,%7,%8};"
                 :: "l"(p), "r"(v[0]), "r"(v[1]), "r"(v[2]), "r"(v[3]),
                    "r"(v[4]), "r"(v[5]), "r"(v[6]), "r"(v[7]) : "memory");
}
__device__ __forceinline__ void stg_256_ef(void* p, const float* f) {
    asm volatile("st.global.L2::evict_first.v8.b32 [%0], {%1,%2,%3,%4,%5,%6,%7,%8};"
                 :: "l"(p),
                    "r"(__float_as_uint(f[0])), "r"(__float_as_uint(f[1])),
                    "r"(__float_as_uint(f[2])), "r"(__float_as_uint(f[3])),
                    "r"(__float_as_uint(f[4])), "r"(__float_as_uint(f[5])),
                    "r"(__float_as_uint(f[6])), "r"(__float_as_uint(f[7])) : "memory");
}

// ---------------------------------------------------------------------------
// Transpose+convert (C,R,R) fp32 -> (R,R,C) fp16 per plane.
// ---------------------------------------------------------------------------
__global__ void tp_kernel(const float* __restrict__ in) {
    __shared__ float tile[NCOMP][33];
    const int tx = threadIdx.x;
    const int ty = threadIdx.y;
    const int x0 = blockIdx.x * 32;
    const int y  = blockIdx.y;
    const int p  = blockIdx.z;

    const float* src = in + ((size_t)(p * NCOMP) * RES + y) * RES + x0;
#pragma unroll
    for (int j = 0; j < 8; j++) {
        const int c = ty + j * 8;
        tile[c][tx] = __ldg(src + (size_t)c * RES * RES + tx);
    }
    __syncthreads();

    const int t = ty * 32 + tx;
    if (t < 128) {
        const int xl = t >> 2;
        const int ch = (t & 3) * 16;
        unsigned v[8];
#pragma unroll
        for (int k = 0; k < 8; k++) {
            const half2 h = __floats2half2_rn(tile[ch + 2 * k][xl],
                                              tile[ch + 2 * k + 1][xl]);
            v[k] = *(const unsigned*)&h;
        }
        __half* dst = g_planeT
            + ((size_t)p * RES * RES + (size_t)y * RES + (x0 + xl)) * NCOMP + ch;
        stg_256_el(dst, v);
    }
}

// ---------------------------------------------------------------------------
// Counting sort: key = Morton2D(bx,by) * 32 + bz.
// (x,y) major -> plane-0 locality is CTA-persistent; z minor keeps planes 1/2
// marching smoothly through L2.
// ---------------------------------------------------------------------------
__device__ __forceinline__ unsigned spread2(unsigned v) {   // 5 bits -> even bits
    v &= 0xFFFF;
    v = (v | (v << 8)) & 0x00FF00FF;
    v = (v | (v << 4)) & 0x0F0F0F0F;
    v = (v | (v << 2)) & 0x33333333;
    v = (v | (v << 1)) & 0x55555555;
    return v;
}
__device__ __forceinline__ unsigned point_bin(float x, float y, float z) {
    const unsigned bx = (unsigned)min(31, max(0, (int)((x + 1.0f) * 16.0f)));
    const unsigned by = (unsigned)min(31, max(0, (int)((y + 1.0f) * 16.0f)));
    const unsigned bz = (unsigned)min(31, max(0, (int)((z + 1.0f) * 16.0f)));
    return ((spread2(bx) | (spread2(by) << 1)) << 5) | bz;
}

// 4 points per thread via 3 coalesced float4 loads (MLP), 4 atomics in flight.
__global__ void hist_kernel(const float* __restrict__ pts, int n_pts) {
    const int j = blockIdx.x * blockDim.x + threadIdx.x;
    const int base = j * 4;
    if (base + 3 < n_pts) {
        const float4* p4 = (const float4*)pts + j * 3;
        const float4 a = __ldg(p4), b = __ldg(p4 + 1), c = __ldg(p4 + 2);
        atomicAdd(&g_binCnt[point_bin(a.x, a.y, a.z)], 1u);
        atomicAdd(&g_binCnt[point_bin(a.w, b.x, b.y)], 1u);
        atomicAdd(&g_binCnt[point_bin(b.z, b.w, c.x)], 1u);
        atomicAdd(&g_binCnt[point_bin(c.y, c.z, c.w)], 1u);
    } else {
        for (int i = base; i < n_pts; i++)
            atomicAdd(&g_binCnt[point_bin(pts[3 * i], pts[3 * i + 1], pts[3 * i + 2])], 1u);
    }
}

// Single block, 1024 threads, warp-shuffle scan (2 barriers).
__global__ void scan_kernel() {
    __shared__ unsigned warpSum[32];
    const int t    = threadIdx.x;
    const int lane = t & 31;
    const int wid  = t >> 5;

    uint4 c[8];
    const uint4* src = (const uint4*)g_binCnt + t * 8;
    unsigned s = 0;
#pragma unroll
    for (int i = 0; i < 8; i++) {
        c[i] = src[i];
        s += c[i].x + c[i].y + c[i].z + c[i].w;
    }
    const unsigned mine = s;
#pragma unroll
    for (int d = 1; d < 32; d <<= 1) {
        const unsigned n = __shfl_up_sync(0xFFFFFFFFu, s, d);
        if (lane >= d) s += n;
    }
    if (lane == 31) warpSum[wid] = s;
    __syncthreads();
    if (wid == 0) {
        unsigned w = warpSum[lane];
#pragma unroll
        for (int d = 1; d < 32; d <<= 1) {
            const unsigned n = __shfl_up_sync(0xFFFFFFFFu, w, d);
            if (lane >= d) w += n;
        }
        warpSum[lane] = w;
    }
    __syncthreads();

    unsigned run = s - mine + (wid ? warpSum[wid - 1] : 0u);
    uint4* dst = (uint4*)g_binCursor + t * 8;
#pragma unroll
    for (int i = 0; i < 8; i++) {
        uint4 o;
        o.x = run; run += c[i].x;
        o.y = run; run += c[i].y;
        o.z = run; run += c[i].z;
        o.w = run; run += c[i].w;
        dst[i] = o;
    }
}

__global__ void scatter_kernel(const float* __restrict__ pts, int n_pts) {
    const int j = blockIdx.x * blockDim.x + threadIdx.x;
    const int base = j * 4;
    if (base + 3 < n_pts) {
        const float4* p4 = (const float4*)pts + j * 3;
        const float4 a = __ldg(p4), b = __ldg(p4 + 1), c = __ldg(p4 + 2);
        const float xs[4] = {a.x, a.w, b.z, c.y};
        const float ys[4] = {a.y, b.x, b.w, c.z};
        const float zs[4] = {a.z, b.y, c.x, c.w};
#pragma unroll
        for (int k = 0; k < 4; k++) {
            const unsigned slot = atomicAdd(&g_binCursor[point_bin(xs[k], ys[k], zs[k])], 1u);
            g_sorted[slot] = make_float4(xs[k], ys[k], zs[k], __int_as_float(base + k));
        }
    } else {
        for (int i = base; i < n_pts; i++) {
            const float x = pts[3 * i], y = pts[3 * i + 1], z = pts[3 * i + 2];
            const unsigned slot = atomicAdd(&g_binCursor[point_bin(x, y, z)], 1u);
            g_sorted[slot] = make_float4(x, y, z, __int_as_float(i));
        }
    }
}

// ---------------------------------------------------------------------------
// Gather: 4 lanes per point (lane owns 16 channels, one 32B load per corner).
// Each 256-thread CTA consumes 1024 CONSECUTIVE sorted points (16 steps of 64)
// so its plane-0 footprint (~37KB) stays L1-resident across all steps.
// ---------------------------------------------------------------------------
__device__ __forceinline__ void acc16(float* a, const unsigned* v, const float w) {
#pragma unroll
    for (int k = 0; k < 8; k++) {
        const float2 f = __half22float2(*(const half2*)&v[k]);
        a[2 * k]     = fmaf(f.x, w, a[2 * k]);
        a[2 * k + 1] = fmaf(f.y, w, a[2 * k + 1]);
    }
}

__global__ void __launch_bounds__(256)
sample_kernel(float* __restrict__ out, int n_pts) {
    const int g   = threadIdx.x >> 2;              // point-group 0..63
    const unsigned sub = (unsigned)(threadIdx.x & 3);
    const int blockBase = blockIdx.x * 1024;
    const char* __restrict__ base = (const char*)g_planeT;
    const unsigned laneoff = sub << 5;
    const float rm1 = (float)(RES - 1);

    for (int i = 0; i < 16; i++) {
        const int pt = blockBase + i * 64 + g;     // 64 consecutive pts per step
        if (pt >= n_pts) return;                   // pt monotone in i

        const float4 pv = __ldg(&g_sorted[pt]);
        const int oidx  = __float_as_int(pv.w);

        const float us[3] = {pv.x, pv.x, pv.y};
        const float vs[3] = {pv.y, pv.z, pv.z};

        float acc[16];
#pragma unroll
        for (int k = 0; k < 16; k++) acc[k] = 0.0f;

#pragma unroll
        for (int p = 0; p < 3; p++) {
            float fx = fminf(fmaxf((us[p] + 1.0f) * 0.5f * rm1, 0.0f), rm1);
            float fy = fminf(fmaxf((vs[p] + 1.0f) * 0.5f * rm1, 0.0f), rm1);
            const float x0f = floorf(fx);
            const float y0f = floorf(fy);
            const float wx = fx - x0f;
            const float wy = fy - y0f;
            const int x0 = (int)x0f;
            const int y0 = (int)y0f;
            const int x1 = min(x0 + 1, RES - 1);
            const int y1 = min(y0 + 1, RES - 1);

            const unsigned r0 = (unsigned)((p * RES + y0) * RES);
            const unsigned r1 = (unsigned)((p * RES + y1) * RES);
            const unsigned o00 = ((r0 + (unsigned)x0) << 7) + laneoff;
            const unsigned o01 = ((r0 + (unsigned)x1) << 7) + laneoff;
            const unsigned o10 = ((r1 + (unsigned)x0) << 7) + laneoff;
            const unsigned o11 = ((r1 + (unsigned)x1) << 7) + laneoff;

            unsigned v00[8], v01[8], v10[8], v11[8];
            ldg_256_el(base + o00, v00);
            ldg_256_el(base + o01, v01);
            ldg_256_el(base + o10, v10);
            ldg_256_el(base + o11, v11);

            const float w00 = (1.0f - wx) * (1.0f - wy);
            const float w01 = wx * (1.0f - wy);
            const float w10 = (1.0f - wx) * wy;
            const float w11 = wx * wy;

            acc16(acc, v00, w00);
            acc16(acc, v01, w01);
            acc16(acc, v10, w10);
            acc16(acc, v11, w11);
        }

        float* orow = out + (size_t)oidx * NCOMP + sub * 16;
        stg_256_ef(orow,     acc);
        stg_256_ef(orow + 8, acc + 8);
    }
}

extern "C" void kernel_launch(void* const* d_in, const int* in_sizes, int n_in,
                              void* d_out, int out_size) {
    const float* in_tensor  = (const float*)d_in[0];   // (N, 3) fp32
    const float* plane_coef = (const float*)d_in[1];   // (3, 64, 512, 512) fp32
    float* out = (float*)d_out;                        // (N, 64) fp32

    const int n_pts = in_sizes[0] / 3;

    // 1) plane reorder + fp16 convert
    dim3 tgrid(RES / 32, RES, 3);
    tp_kernel<<<tgrid, dim3(32, 8)>>>(plane_coef);

    // 2) Morton2D(x,y)-major counting sort
    void* cnt_ptr = nullptr;
    cudaGetSymbolAddress(&cnt_ptr, g_binCnt);
    cudaMemsetAsync(cnt_ptr, 0, NBIN * sizeof(unsigned));
    const int nb4 = (n_pts / 4 + 255) / 256;
    hist_kernel<<<nb4, 256>>>(in_tensor, n_pts);
    scan_kernel<<<1, 1024>>>();
    scatter_kernel<<<nb4, 256>>>(in_tensor, n_pts);

    // 3) gather: each CTA owns 1024 consecutive sorted points
    const int nblk = (n_pts + 1023) / 1024;
    sample_kernel<<<nblk, 256>>>(out, n_pts);
}

// round 14
// speedup vs baseline: 1.5208x; 1.5208x over previous
#include <cuda_runtime.h>
#include <cuda_fp16.h>

#define RES    512
#define NCOMP  64
#define NPTS_MAX 1048576
#define NBIN   32768          // 32^3 Morton-3D bins

// Channel-last fp16 scratch: [plane][y][x][c]  = 100.5 MB
__device__ __half g_planeT[3ull * RES * RES * NCOMP];
// Sort scratch
__device__ unsigned g_binCnt[NBIN];
__device__ unsigned g_binCursor[NBIN];
__device__ unsigned g_sortedIdx[NPTS_MAX];   // original point index, bin-sorted

// ---------------- 256-bit accessors (sm_103a evict hints need v8.b32) ------
__device__ __forceinline__ void ldg_256_el(const void* p, unsigned* v) {
    asm("ld.global.nc.L2::evict_last.v8.b32 {%0,%1,%2,%3,%4,%5,%6,%7}, [%8];"
        : "=r"(v[0]), "=r"(v[1]), "=r"(v[2]), "=r"(v[3]),
          "=r"(v[4]), "=r"(v[5]), "=r"(v[6]), "=r"(v[7])
        : "l"(p));
}
__device__ __forceinline__ void stg_256_el(void* p, const unsigned* v) {
    asm volatile("st.global.L2::evict_last.v8.b32 [%0], {%1,%2,%3,%4,%5,%6,%7,%8};"
                 :: "l"(p), "r"(v[0]), "r"(v[1]), "r"(v[2]), "r"(v[3]),
                    "r"(v[4]), "r"(v[5]), "r"(v[6]), "r"(v[7]) : "memory");
}
__device__ __forceinline__ void stg_256_ef(void* p, const float* f) {
    asm volatile("st.global.L2::evict_first.v8.b32 [%0], {%1,%2,%3,%4,%5,%6,%7,%8};"
                 :: "l"(p),
                    "r"(__float_as_uint(f[0])), "r"(__float_as_uint(f[1])),
                    "r"(__float_as_uint(f[2])), "r"(__float_as_uint(f[3])),
                    "r"(__float_as_uint(f[4])), "r"(__float_as_uint(f[5])),
                    "r"(__float_as_uint(f[6])), "r"(__float_as_uint(f[7])) : "memory");
}

// ---------------------------------------------------------------------------
// Transpose+convert (C,R,R) fp32 -> (R,R,C) fp16 per plane.
// ---------------------------------------------------------------------------
__global__ void tp_kernel(const float* __restrict__ in) {
    __shared__ float tile[NCOMP][33];
    const int tx = threadIdx.x;
    const int ty = threadIdx.y;
    const int x0 = blockIdx.x * 32;
    const int y  = blockIdx.y;
    const int p  = blockIdx.z;

    const float* src = in + ((size_t)(p * NCOMP) * RES + y) * RES + x0;
#pragma unroll
    for (int j = 0; j < 8; j++) {
        const int c = ty + j * 8;
        tile[c][tx] = __ldg(src + (size_t)c * RES * RES + tx);
    }
    __syncthreads();

    const int t = ty * 32 + tx;
    if (t < 128) {
        const int xl = t >> 2;
        const int ch = (t & 3) * 16;
        unsigned v[8];
#pragma unroll
        for (int k = 0; k < 8; k++) {
            const half2 h = __floats2half2_rn(tile[ch + 2 * k][xl],
                                              tile[ch + 2 * k + 1][xl]);
            v[k] = *(const unsigned*)&h;
        }
        __half* dst = g_planeT
            + ((size_t)p * RES * RES + (size_t)y * RES + (x0 + xl)) * NCOMP + ch;
        stg_256_el(dst, v);
    }
}

// ---------------------------------------------------------------------------
// Morton-3D 32^3 counting sort (index-only payload).
// ---------------------------------------------------------------------------
__device__ __forceinline__ unsigned spread3(unsigned v) {
    v &= 0x3FF;
    v = (v | (v << 16)) & 0x030000FF;
    v = (v | (v << 8))  & 0x0300F00F;
    v = (v | (v << 4))  & 0x030C30C3;
    v = (v | (v << 2))  & 0x09249249;
    return v;
}
__device__ __forceinline__ unsigned point_bin(float x, float y, float z) {
    const unsigned bx = (unsigned)min(31, max(0, (int)((x + 1.0f) * 16.0f)));
    const unsigned by = (unsigned)min(31, max(0, (int)((y + 1.0f) * 16.0f)));
    const unsigned bz = (unsigned)min(31, max(0, (int)((z + 1.0f) * 16.0f)));
    return spread3(bx) | (spread3(by) << 1) | (spread3(bz) << 2);
}

__global__ void hist_kernel(const float* __restrict__ pts, int n_pts) {
    const int i = blockIdx.x * blockDim.x + threadIdx.x;
    if (i >= n_pts) return;
    const float x = pts[3 * (size_t)i + 0];
    const float y = pts[3 * (size_t)i + 1];
    const float z = pts[3 * (size_t)i + 2];
    atomicAdd(&g_binCnt[point_bin(x, y, z)], 1u);
}

// Single block, 1024 threads, warp-shuffle scan.
__global__ void scan_kernel() {
    __shared__ unsigned warpSum[32];
    const int t    = threadIdx.x;
    const int lane = t & 31;
    const int wid  = t >> 5;

    uint4 c[8];
    const uint4* src = (const uint4*)g_binCnt + t * 8;
    unsigned s = 0;
#pragma unroll
    for (int i = 0; i < 8; i++) {
        c[i] = src[i];
        s += c[i].x + c[i].y + c[i].z + c[i].w;
    }
    const unsigned mine = s;
#pragma unroll
    for (int d = 1; d < 32; d <<= 1) {
        const unsigned n = __shfl_up_sync(0xFFFFFFFFu, s, d);
        if (lane >= d) s += n;
    }
    if (lane == 31) warpSum[wid] = s;
    __syncthreads();
    if (wid == 0) {
        unsigned w = warpSum[lane];
#pragma unroll
        for (int d = 1; d < 32; d <<= 1) {
            const unsigned n = __shfl_up_sync(0xFFFFFFFFu, w, d);
            if (lane >= d) w += n;
        }
        warpSum[lane] = w;
    }
    __syncthreads();

    unsigned run = s - mine + (wid ? warpSum[wid - 1] : 0u);
    uint4* dst = (uint4*)g_binCursor + t * 8;
#pragma unroll
    for (int i = 0; i < 8; i++) {
        uint4 o;
        o.x = run; run += c[i].x;
        o.y = run; run += c[i].y;
        o.z = run; run += c[i].z;
        o.w = run; run += c[i].w;
        dst[i] = o;
    }
}

// Payload is just the 4B original index (was 16B float4): 4x less scatter
// store traffic, denser lines within each bin's slot range.
__global__ void scatter_kernel(const float* __restrict__ pts, int n_pts) {
    const int i = blockIdx.x * blockDim.x + threadIdx.x;
    if (i >= n_pts) return;
    const float x = pts[3 * (size_t)i + 0];
    const float y = pts[3 * (size_t)i + 1];
    const float z = pts[3 * (size_t)i + 2];
    const unsigned slot = atomicAdd(&g_binCursor[point_bin(x, y, z)], 1u);
    g_sortedIdx[slot] = (unsigned)i;
}

// ---------------------------------------------------------------------------
// Gather: 4 lanes per point, lane owns 16 channels (one 32B load per corner;
// 4 lanes = one 128B texel line). Morton-3D order -> L2/L1 texel reuse.
// Coords re-read from pts via sorted index (12MB -> L2-resident after hist).
// ---------------------------------------------------------------------------
__device__ __forceinline__ void acc16(float* a, const unsigned* v, const float w) {
#pragma unroll
    for (int k = 0; k < 8; k++) {
        const float2 f = __half22float2(*(const half2*)&v[k]);
        a[2 * k]     = fmaf(f.x, w, a[2 * k]);
        a[2 * k + 1] = fmaf(f.y, w, a[2 * k + 1]);
    }
}

__global__ void __launch_bounds__(256)
sample_kernel(const float* __restrict__ pts, float* __restrict__ out, int n_pts) {
    const int tid = (int)(blockIdx.x * blockDim.x + threadIdx.x);
    const int pt  = tid >> 2;
    if (pt >= n_pts) return;
    const unsigned sub = (unsigned)(tid & 3);      // channels [16*sub, 16*sub+16)

    const unsigned oidx = __ldg(&g_sortedIdx[pt]); // broadcast across 4 lanes
    const float px = __ldg(pts + 3 * (size_t)oidx + 0);
    const float py = __ldg(pts + 3 * (size_t)oidx + 1);
    const float pz = __ldg(pts + 3 * (size_t)oidx + 2);

    const float us[3] = {px, px, py};
    const float vs[3] = {py, pz, pz};
    const float rm1 = (float)(RES - 1);

    float acc[16];
#pragma unroll
    for (int k = 0; k < 16; k++) acc[k] = 0.0f;

    const char* __restrict__ base = (const char*)g_planeT;
    const unsigned laneoff = sub << 5;             // 32B per lane within 128B texel

#pragma unroll
    for (int p = 0; p < 3; p++) {
        float fx = fminf(fmaxf((us[p] + 1.0f) * 0.5f * rm1, 0.0f), rm1);
        float fy = fminf(fmaxf((vs[p] + 1.0f) * 0.5f * rm1, 0.0f), rm1);
        const float x0f = floorf(fx);
        const float y0f = floorf(fy);
        const float wx = fx - x0f;
        const float wy = fy - y0f;
        const int x0 = (int)x0f;
        const int y0 = (int)y0f;
        const int x1 = min(x0 + 1, RES - 1);
        const int y1 = min(y0 + 1, RES - 1);

        const unsigned r0 = (unsigned)((p * RES + y0) * RES);
        const unsigned r1 = (unsigned)((p * RES + y1) * RES);
        const unsigned o00 = ((r0 + (unsigned)x0) << 7) + laneoff;
        const unsigned o01 = ((r0 + (unsigned)x1) << 7) + laneoff;
        const unsigned o10 = ((r1 + (unsigned)x0) << 7) + laneoff;
        const unsigned o11 = ((r1 + (unsigned)x1) << 7) + laneoff;

        unsigned v00[8], v01[8], v10[8], v11[8];
        ldg_256_el(base + o00, v00);
        ldg_256_el(base + o01, v01);
        ldg_256_el(base + o10, v10);
        ldg_256_el(base + o11, v11);

        const float w00 = (1.0f - wx) * (1.0f - wy);
        const float w01 = wx * (1.0f - wy);
        const float w10 = (1.0f - wx) * wy;
        const float w11 = wx * wy;

        acc16(acc, v00, w00);
        acc16(acc, v01, w01);
        acc16(acc, v10, w10);
        acc16(acc, v11, w11);
    }

    float* orow = out + (size_t)oidx * NCOMP + sub * 16;
    stg_256_ef(orow,     acc);
    stg_256_ef(orow + 8, acc + 8);
}

extern "C" void kernel_launch(void* const* d_in, const int* in_sizes, int n_in,
                              void* d_out, int out_size) {
    const float* in_tensor  = (const float*)d_in[0];   // (N, 3) fp32
    const float* plane_coef = (const float*)d_in[1];   // (3, 64, 512, 512) fp32
    float* out = (float*)d_out;                        // (N, 64) fp32

    const int n_pts = in_sizes[0] / 3;
    const int nb256 = (n_pts + 255) / 256;

    // 1) plane reorder + fp16 convert
    dim3 tgrid(RES / 32, RES, 3);
    tp_kernel<<<tgrid, dim3(32, 8)>>>(plane_coef);

    // 2) Morton-3D counting sort (index payload only)
    void* cnt_ptr = nullptr;
    cudaGetSymbolAddress(&cnt_ptr, g_binCnt);
    cudaMemsetAsync(cnt_ptr, 0, NBIN * sizeof(unsigned));
    hist_kernel<<<nb256, 256>>>(in_tensor, n_pts);
    scan_kernel<<<1, 1024>>>();
    scatter_kernel<<<nb256, 256>>>(in_tensor, n_pts);

    // 3) gather in Morton order: 4 lanes per point
    const int nblk = (n_pts + 63) / 64;
    sample_kernel<<<nblk, 256>>>(in_tensor, out, n_pts);
}

// round 17
// speedup vs baseline: 1.6050x; 1.0554x over previous
#include <cuda_runtime.h>
#include <cuda_fp16.h>

#define RES    512
#define NCOMP  64
#define NPTS_MAX 1048576
#define NBIN   32768          // 32^3 Morton-3D bins
#define TP_BLOCKS (16 * 512 * 3)   // 24576

// Channel-last fp16 scratch: [plane][y][x][c]  = 100.5 MB
__device__ __half g_planeT[3ull * RES * RES * NCOMP];
// Sort scratch
__device__ unsigned g_binCnt[NBIN];
__device__ unsigned g_binStart[NBIN];     // exclusive prefix (read-only after scan)
__device__ unsigned g_packed[NPTS_MAX];   // (rank << 15) | bin
__device__ float4   g_sorted[NPTS_MAX];   // (x, y, z, orig_idx bits)

// ---------------- 256-bit accessors (sm_103a evict hints need v8.b32) ------
__device__ __forceinline__ void ldg_256_el(const void* p, unsigned* v) {
    asm("ld.global.nc.L2::evict_last.v8.b32 {%0,%1,%2,%3,%4,%5,%6,%7}, [%8];"
        : "=r"(v[0]), "=r"(v[1]), "=r"(v[2]), "=r"(v[3]),
          "=r"(v[4]), "=r"(v[5]), "=r"(v[6]), "=r"(v[7])
        : "l"(p));
}
__device__ __forceinline__ void stg_256_el(void* p, const unsigned* v) {
    asm volatile("st.global.L2::evict_last.v8.b32 [%0], {%1,%2,%3,%4,%5,%6,%7,%8};"
                 :: "l"(p), "r"(v[0]), "r"(v[1]), "r"(v[2]), "r"(v[3]),
                    "r"(v[4]), "r"(v[5]), "r"(v[6]), "r"(v[7]) : "memory");
}
__device__ __forceinline__ void stg_256_ef(void* p, const float* f) {
    asm volatile("st.global.L2::evict_first.v8.b32 [%0], {%1,%2,%3,%4,%5,%6,%7,%8};"
                 :: "l"(p),
                    "r"(__float_as_uint(f[0])), "r"(__float_as_uint(f[1])),
                    "r"(__float_as_uint(f[2])), "r"(__float_as_uint(f[3])),
                    "r"(__float_as_uint(f[4])), "r"(__float_as_uint(f[5])),
                    "r"(__float_as_uint(f[6])), "r"(__float_as_uint(f[7])) : "memory");
}

// ---------------------------------------------------------------------------
// Morton-3D bin key.
// ---------------------------------------------------------------------------
__device__ __forceinline__ unsigned spread3(unsigned v) {
    v &= 0x3FF;
    v = (v | (v << 16)) & 0x030000FF;
    v = (v | (v << 8))  & 0x0300F00F;
    v = (v | (v << 4))  & 0x030C30C3;
    v = (v | (v << 2))  & 0x09249249;
    return v;
}
__device__ __forceinline__ unsigned point_bin(float x, float y, float z) {
    const unsigned bx = (unsigned)min(31, max(0, (int)((x + 1.0f) * 16.0f)));
    const unsigned by = (unsigned)min(31, max(0, (int)((y + 1.0f) * 16.0f)));
    const unsigned bz = (unsigned)min(31, max(0, (int)((z + 1.0f) * 16.0f)));
    return spread3(bx) | (spread3(by) << 1) | (spread3(bz) << 2);
}

// ---------------------------------------------------------------------------
// Fused kernel: blocks [0, TP_BLOCKS) do transpose+fp16-convert;
// blocks [TP_BLOCKS, ...) do histogram + rank capture. The small hist
// workload hides inside the DRAM-bound transpose — single-stream overlap.
// ---------------------------------------------------------------------------
__global__ void __launch_bounds__(256)
tp_hist_kernel(const float* __restrict__ in, int n_pts) {
    const int b = blockIdx.x;
    const int t = threadIdx.x;

    if (b < TP_BLOCKS) {
        // ---- transpose part: b -> (x-tile, y, plane) ----
        __shared__ float tile[NCOMP][33];
        const int tx = t & 31;
        const int ty = t >> 5;
        const int x0 = (b & 15) * 32;
        const int y  = (b >> 4) & 511;
        const int p  = b >> 13;

        const float* src = in + ((size_t)(p * NCOMP) * RES + y) * RES + x0;
#pragma unroll
        for (int j = 0; j < 8; j++) {
            const int c = ty + j * 8;
            tile[c][tx] = __ldg(src + (size_t)c * RES * RES + tx);
        }
        __syncthreads();

        if (t < 128) {
            const int xl = t >> 2;
            const int ch = (t & 3) * 16;
            unsigned v[8];
#pragma unroll
            for (int k = 0; k < 8; k++) {
                const half2 h = __floats2half2_rn(tile[ch + 2 * k][xl],
                                                  tile[ch + 2 * k + 1][xl]);
                v[k] = *(const unsigned*)&h;
            }
            __half* dst = g_planeT
                + ((size_t)p * RES * RES + (size_t)y * RES + (x0 + xl)) * NCOMP + ch;
            stg_256_el(dst, v);
        }
    } else {
        // ---- histogram + rank part ----
        // NOTE: 'in' here is the points array — passed separately below.
    }
}

// hist as its own block range needs the points pointer; do it via a second
// argument and a branch instead (cleaner): combined kernel takes both.
__global__ void __launch_bounds__(256)
fused_kernel(const float* __restrict__ planes, const float* __restrict__ pts,
             int n_pts) {
    const int b = blockIdx.x;
    const int t = threadIdx.x;

    if (b < TP_BLOCKS) {
        __shared__ float tile[NCOMP][33];
        const int tx = t & 31;
        const int ty = t >> 5;
        const int x0 = (b & 15) * 32;
        const int y  = (b >> 4) & 511;
        const int p  = b >> 13;

        const float* src = planes + ((size_t)(p * NCOMP) * RES + y) * RES + x0;
#pragma unroll
        for (int j = 0; j < 8; j++) {
            const int c = ty + j * 8;
            tile[c][tx] = __ldg(src + (size_t)c * RES * RES + tx);
        }
        __syncthreads();

        if (t < 128) {
            const int xl = t >> 2;
            const int ch = (t & 3) * 16;
            unsigned v[8];
#pragma unroll
            for (int k = 0; k < 8; k++) {
                const half2 h = __floats2half2_rn(tile[ch + 2 * k][xl],
                                                  tile[ch + 2 * k + 1][xl]);
                v[k] = *(const unsigned*)&h;
            }
            __half* dst = g_planeT
                + ((size_t)p * RES * RES + (size_t)y * RES + (x0 + xl)) * NCOMP + ch;
            stg_256_el(dst, v);
        }
    } else {
        const int i = (b - TP_BLOCKS) * 256 + t;
        if (i < n_pts) {
            const float x = pts[3 * (size_t)i + 0];
            const float y = pts[3 * (size_t)i + 1];
            const float z = pts[3 * (size_t)i + 2];
            const unsigned bin  = point_bin(x, y, z);
            const unsigned rank = atomicAdd(&g_binCnt[bin], 1u);
            g_packed[i] = (rank << 15) | bin;      // rank < 2^17 guaranteed
        }
    }
}

// Single block, 1024 threads, warp-shuffle scan. Writes exclusive prefix to
// g_binStart (never mutated afterwards).
__global__ void scan_kernel() {
    __shared__ unsigned warpSum[32];
    const int t    = threadIdx.x;
    const int lane = t & 31;
    const int wid  = t >> 5;

    uint4 c[8];
    const uint4* src = (const uint4*)g_binCnt + t * 8;
    unsigned s = 0;
#pragma unroll
    for (int i = 0; i < 8; i++) {
        c[i] = src[i];
        s += c[i].x + c[i].y + c[i].z + c[i].w;
    }
    const unsigned mine = s;
#pragma unroll
    for (int d = 1; d < 32; d <<= 1) {
        const unsigned n = __shfl_up_sync(0xFFFFFFFFu, s, d);
        if (lane >= d) s += n;
    }
    if (lane == 31) warpSum[wid] = s;
    __syncthreads();
    if (wid == 0) {
        unsigned w = warpSum[lane];
#pragma unroll
        for (int d = 1; d < 32; d <<= 1) {
            const unsigned n = __shfl_up_sync(0xFFFFFFFFu, w, d);
            if (lane >= d) w += n;
        }
        warpSum[lane] = w;
    }
    __syncthreads();

    unsigned run = s - mine + (wid ? warpSum[wid - 1] : 0u);
    uint4* dst = (uint4*)g_binStart + t * 8;
#pragma unroll
    for (int i = 0; i < 8; i++) {
        uint4 o;
        o.x = run; run += c[i].x;
        o.y = run; run += c[i].y;
        o.z = run; run += c[i].z;
        o.w = run; run += c[i].w;
        dst[i] = o;
    }
}

// Atomic-free scatter: slot = binStart[bin] + rank (rank captured in hist).
__global__ void scatter_kernel(const float* __restrict__ pts, int n_pts) {
    const int i = blockIdx.x * blockDim.x + threadIdx.x;
    if (i >= n_pts) return;
    const unsigned packed = g_packed[i];
    const unsigned bin  = packed & 0x7FFFu;
    const unsigned rank = packed >> 15;
    const unsigned slot = __ldg(&g_binStart[bin]) + rank;
    const float x = pts[3 * (size_t)i + 0];
    const float y = pts[3 * (size_t)i + 1];
    const float z = pts[3 * (size_t)i + 2];
    g_sorted[slot] = make_float4(x, y, z, __int_as_float(i));
}

// ---------------------------------------------------------------------------
// Gather: 4 lanes per point, lane owns 16 channels (one 32B load per corner;
// 4 lanes = one 128B texel line). Morton-3D order -> L2 texel reuse.
// (Identical to the R8 sample kernel that measured ~120us.)
// ---------------------------------------------------------------------------
__device__ __forceinline__ void acc16(float* a, const unsigned* v, const float w) {
#pragma unroll
    for (int k = 0; k < 8; k++) {
        const float2 f = __half22float2(*(const half2*)&v[k]);
        a[2 * k]     = fmaf(f.x, w, a[2 * k]);
        a[2 * k + 1] = fmaf(f.y, w, a[2 * k + 1]);
    }
}

__global__ void __launch_bounds__(256)
sample_kernel(float* __restrict__ out, int n_pts) {
    const int tid = (int)(blockIdx.x * blockDim.x + threadIdx.x);
    const int pt  = tid >> 2;
    if (pt >= n_pts) return;
    const unsigned sub = (unsigned)(tid & 3);      // channels [16*sub, 16*sub+16)

    const float4 pv = __ldg(&g_sorted[pt]);        // broadcast across 4 lanes
    const int oidx  = __float_as_int(pv.w);

    const float us[3] = {pv.x, pv.x, pv.y};
    const float vs[3] = {pv.y, pv.z, pv.z};
    const float rm1 = (float)(RES - 1);

    float acc[16];
#pragma unroll
    for (int k = 0; k < 16; k++) acc[k] = 0.0f;

    const char* __restrict__ base = (const char*)g_planeT;
    const unsigned laneoff = sub << 5;             // 32B per lane within 128B texel

#pragma unroll
    for (int p = 0; p < 3; p++) {
        float fx = fminf(fmaxf((us[p] + 1.0f) * 0.5f * rm1, 0.0f), rm1);
        float fy = fminf(fmaxf((vs[p] + 1.0f) * 0.5f * rm1, 0.0f), rm1);
        const float x0f = floorf(fx);
        const float y0f = floorf(fy);
        const float wx = fx - x0f;
        const float wy = fy - y0f;
        const int x0 = (int)x0f;
        const int y0 = (int)y0f;
        const int x1 = min(x0 + 1, RES - 1);
        const int y1 = min(y0 + 1, RES - 1);

        const unsigned r0 = (unsigned)((p * RES + y0) * RES);
        const unsigned r1 = (unsigned)((p * RES + y1) * RES);
        const unsigned o00 = ((r0 + (unsigned)x0) << 7) + laneoff;
        const unsigned o01 = ((r0 + (unsigned)x1) << 7) + laneoff;
        const unsigned o10 = ((r1 + (unsigned)x0) << 7) + laneoff;
        const unsigned o11 = ((r1 + (unsigned)x1) << 7) + laneoff;

        unsigned v00[8], v01[8], v10[8], v11[8];
        ldg_256_el(base + o00, v00);
        ldg_256_el(base + o01, v01);
        ldg_256_el(base + o10, v10);
        ldg_256_el(base + o11, v11);

        const float w00 = (1.0f - wx) * (1.0f - wy);
        const float w01 = wx * (1.0f - wy);
        const float w10 = (1.0f - wx) * wy;
        const float w11 = wx * wy;

        acc16(acc, v00, w00);
        acc16(acc, v01, w01);
        acc16(acc, v10, w10);
        acc16(acc, v11, w11);
    }

    float* orow = out + (size_t)oidx * NCOMP + sub * 16;
    stg_256_ef(orow,     acc);
    stg_256_ef(orow + 8, acc + 8);
}

extern "C" void kernel_launch(void* const* d_in, const int* in_sizes, int n_in,
                              void* d_out, int out_size) {
    const float* in_tensor  = (const float*)d_in[0];   // (N, 3) fp32
    const float* plane_coef = (const float*)d_in[1];   // (3, 64, 512, 512) fp32
    float* out = (float*)d_out;                        // (N, 64) fp32

    const int n_pts = in_sizes[0] / 3;
    const int hist_blocks = (n_pts + 255) / 256;

    // 0) zero bin counters
    void* cnt_ptr = nullptr;
    cudaGetSymbolAddress(&cnt_ptr, g_binCnt);
    cudaMemsetAsync(cnt_ptr, 0, NBIN * sizeof(unsigned));

    // 1) fused transpose + histogram (hist hides inside DRAM-bound transpose)
    fused_kernel<<<TP_BLOCKS + hist_blocks, 256>>>(plane_coef, in_tensor, n_pts);

    // 2) scan (exclusive prefix -> g_binStart)
    scan_kernel<<<1, 1024>>>();

    // 3) atomic-free scatter
    scatter_kernel<<<hist_blocks, 256>>>(in_tensor, n_pts);

    // 4) gather in Morton order: 4 lanes per point
    const int nblk = (n_pts + 63) / 64;
    sample_kernel<<<nblk, 256>>>(out, n_pts);
}